// round 4
// baseline (speedup 1.0000x reference)
#include <cuda_runtime.h>
#include <cstdint>
#include <math.h>

#define BATCH 2048
#define DM    1024
#define RNUM  64
#define KC    3072
#define KT    32
#define NKT   (KC / KT)     // 96
#define STG   55296         // per-stage smem bytes: A 128*144 + B 256*144
#define ASZ   18432
#define CSTR  257
#define TIE_EPS 1e-4f

// ---------------- device scratch ----------------
__device__ float g_dv[BATCH * DM];          // sigmoid(x@Wa)*tanh(x@Wd)
__device__ float g_xc[BATCH * KC];          // [xh | xh | xl], k-permuted
__device__ float g_wpc[RNUM * 256 * KC];    // W_perm^T: [Wh | Wl | Wh], k-permuted
__device__ float g_wc[2 * DM * KC];         // interleaved (d,a) cols of [Wd|Wa]^T, split

// ---------------- helpers ----------------
__device__ __forceinline__ uint32_t smem_u32(const void* p) {
    uint32_t a;
    asm("{ .reg .u64 t; cvta.to.shared.u64 t, %1; cvt.u32.u64 %0, t; }" : "=r"(a) : "l"(p));
    return a;
}
__device__ __forceinline__ float f2tf32(float x) {
    uint32_t r; asm("cvt.rna.tf32.f32 %0, %1;" : "=r"(r) : "f"(x));
    return __uint_as_float(r);
}
__device__ __forceinline__ int p16(int k) {
    return (k & ~15) | ((k & 3) << 2) | ((k >> 2) & 3);
}
__device__ __forceinline__ float4 ldsf4(uint32_t a) {
    float4 r;
    asm volatile("ld.shared.v4.f32 {%0,%1,%2,%3}, [%4];"
                 : "=f"(r.x), "=f"(r.y), "=f"(r.z), "=f"(r.w) : "r"(a));
    return r;
}
#define CPA16(dst, src) asm volatile("cp.async.cg.shared.global [%0], [%1], 16;" :: "r"(dst), "l"(src))
#define CP_COMMIT() asm volatile("cp.async.commit_group;" ::: "memory")
#define CP_WAIT(N)  asm volatile("cp.async.wait_group %0;" :: "n"(N) : "memory")

#define MMA_TF32(c, a0, a1, a2, a3, b0, b1) \
    asm volatile("mma.sync.aligned.m16n8k8.row.col.f32.tf32.tf32.f32 " \
        "{%0,%1,%2,%3}, {%4,%5,%6,%7}, {%8,%9}, {%0,%1,%2,%3};" \
        : "+f"((c)[0]), "+f"((c)[1]), "+f"((c)[2]), "+f"((c)[3]) \
        : "r"(__float_as_uint(a0)), "r"(__float_as_uint(a1)), \
          "r"(__float_as_uint(a2)), "r"(__float_as_uint(a3)), \
          "r"(__float_as_uint(b0)), "r"(__float_as_uint(b1)))

// ---------------- prep kernels ----------------
__global__ void conv_x(const float* __restrict__ x) {
    int g = blockIdx.x * 256 + threadIdx.x;
    int m = g >> 10, k = g & 1023;
    float v = x[g];
    float hi = f2tf32(v);
    size_t b = (size_t)m * KC + p16(k);
    g_xc[b]        = hi;
    g_xc[b + 1024] = hi;
    g_xc[b + 2048] = v - hi;
}

__global__ void tr_wp(const float* __restrict__ Wp) {
    __shared__ float t[32][33];
    int n0 = blockIdx.x * 32, k0 = blockIdx.y * 32;
    int tx = threadIdx.x, ty = threadIdx.y;
    #pragma unroll
    for (int i = 0; i < 4; i++)
        t[ty + i * 8][tx] = Wp[(size_t)(k0 + ty + i * 8) * (RNUM * 256) + n0 + tx];
    __syncthreads();
    #pragma unroll
    for (int i = 0; i < 4; i++) {
        int rr = ty + i * 8;
        float v = t[tx][rr];
        float hi = f2tf32(v);
        int p = p16(k0 + tx);
        size_t b = (size_t)(n0 + rr) * KC;
        g_wpc[b + p]        = hi;
        g_wpc[b + 1024 + p] = v - hi;
        g_wpc[b + 2048 + p] = hi;
    }
}

__global__ void tr_wc(const float* __restrict__ Wd, const float* __restrict__ Wa) {
    __shared__ float t[2][32][33];
    int n0 = blockIdx.x * 32, k0 = blockIdx.y * 32;
    int tx = threadIdx.x, ty = threadIdx.y;
    #pragma unroll
    for (int i = 0; i < 4; i++) {
        int rr = ty + i * 8;
        t[0][rr][tx] = Wd[(size_t)(k0 + rr) * DM + n0 + tx];
        t[1][rr][tx] = Wa[(size_t)(k0 + rr) * DM + n0 + tx];
    }
    __syncthreads();
    #pragma unroll
    for (int i = 0; i < 4; i++) {
        int rr = ty + i * 8;
        int p = p16(k0 + tx);
        #pragma unroll
        for (int s = 0; s < 2; s++) {
            float v = t[s][tx][rr];
            float hi = f2tf32(v);
            size_t b = (size_t)(2 * (n0 + rr) + s) * KC;
            g_wc[b + p]        = hi;
            g_wc[b + 1024 + p] = v - hi;
            g_wc[b + 2048 + p] = hi;
        }
    }
}

// ---------------- GEMM building blocks ----------------
__device__ __forceinline__ void ld_tile(uint32_t sA, uint32_t sB,
                                        const float* Ag, const float* Bg,
                                        int gk, int tid) {
    #pragma unroll
    for (int i = 0; i < 4; i++) {
        int v = tid + i * 256, row = v >> 3, c = v & 7;
        CPA16(sA + row * 144 + c * 16, (const char*)(Ag + (size_t)row * KC + gk) + c * 16);
    }
    #pragma unroll
    for (int i = 0; i < 8; i++) {
        int v = tid + i * 256, row = v >> 3, c = v & 7;
        CPA16(sB + row * 144 + c * 16, (const char*)(Bg + (size_t)row * KC + gk) + c * 16);
    }
}

__device__ __forceinline__ void compute_tile(uint32_t sA, uint32_t sB,
                                             int wm, int wn, int gid, int qc,
                                             float acc[4][8][4]) {
    #pragma unroll
    for (int g16 = 0; g16 < 2; g16++) {
        float4 alo[4], ahi[4], bb[8];
        uint32_t coff = (g16 * 4 + qc) * 16;
        #pragma unroll
        for (int fm = 0; fm < 4; fm++) {
            uint32_t a = sA + (wm + fm * 16 + gid) * 144 + coff;
            alo[fm] = ldsf4(a);
            ahi[fm] = ldsf4(a + 8 * 144);
        }
        #pragma unroll
        for (int fn = 0; fn < 8; fn++)
            bb[fn] = ldsf4(sB + (wn + fn * 8 + gid) * 144 + coff);
        #pragma unroll
        for (int fm = 0; fm < 4; fm++)
            #pragma unroll
            for (int fn = 0; fn < 8; fn++) {
                MMA_TF32(acc[fm][fn], alo[fm].x, ahi[fm].x, alo[fm].y, ahi[fm].y,
                         bb[fn].x, bb[fn].y);
                MMA_TF32(acc[fm][fn], alo[fm].z, ahi[fm].z, alo[fm].w, ahi[fm].w,
                         bb[fn].z, bb[fn].w);
            }
    }
}

#define GEMM_MAINLOOP(Ag, Bg)                                                   \
    float acc[4][8][4] = {};                                                    \
    ld_tile(sb, sb + ASZ, Ag, Bg, 0, tid);                                      \
    CP_COMMIT();                                                                \
    for (int kt = 0; kt < NKT; kt++) {                                          \
        int s = kt & 1;                                                         \
        uint32_t st = sb + s * STG;                                             \
        if (kt + 1 < NKT) {                                                     \
            ld_tile(sb + (s ^ 1) * STG, sb + (s ^ 1) * STG + ASZ, Ag, Bg,       \
                    (kt + 1) * KT, tid);                                        \
            CP_COMMIT();                                                        \
            CP_WAIT(1);                                                         \
        } else CP_WAIT(0);                                                      \
        __syncthreads();                                                        \
        compute_tile(st, st + ASZ, wm, wn, gid, qc, acc);                       \
        __syncthreads();                                                        \
    }

// ---------------- exact recompute for near-tie blocks (rare path) ----------------
// lane j of a 16-lane half recomputes its column's 16 logits exactly, then
// runs a double-precision sinkhorn; returns the exact argmax row.
__device__ __noinline__ int exact_argmax(int bg, int r, int j) {
    const float* xr = g_xc + (size_t)bg * KC;
    const float* wb = g_wpc + ((size_t)r * 256 + j) * KC;
    double L[16];
    #pragma unroll 1
    for (int i = 0; i < 16; i++) {
        const float* wr = wb + (size_t)i * 16 * KC;
        float s = 0.f, comp = 0.f;
        #pragma unroll 1
        for (int c = 0; c < 64; c++) {
            float p = 0.f;
            #pragma unroll
            for (int t = 0; t < 16; t++) {
                int k = c * 16 + t;
                p = fmaf(xr[k] + xr[k + 2048], wr[k] + wr[k + 1024], p);
            }
            float y = p - comp, t2 = s + y;
            comp = (t2 - s) - y;
            s = t2;
        }
        L[i] = 2.0 * (double)s;
    }
    const unsigned FULL = 0xffffffffu;
    #pragma unroll 1
    for (int it = 0; it < 5; it++) {
        #pragma unroll 1
        for (int i = 0; i < 16; i++) {
            double mx = L[i];
            mx = fmax(mx, __shfl_xor_sync(FULL, mx, 1));
            mx = fmax(mx, __shfl_xor_sync(FULL, mx, 2));
            mx = fmax(mx, __shfl_xor_sync(FULL, mx, 4));
            mx = fmax(mx, __shfl_xor_sync(FULL, mx, 8));
            double e = exp(L[i] - mx);
            e += __shfl_xor_sync(FULL, e, 1);
            e += __shfl_xor_sync(FULL, e, 2);
            e += __shfl_xor_sync(FULL, e, 4);
            e += __shfl_xor_sync(FULL, e, 8);
            L[i] -= mx + log(e);
        }
        double mx = L[0];
        #pragma unroll
        for (int i = 1; i < 16; i++) mx = fmax(mx, L[i]);
        double ss = 0.0;
        #pragma unroll
        for (int i = 0; i < 16; i++) ss += exp(L[i] - mx);
        double sub = mx + log(ss);
        #pragma unroll
        for (int i = 0; i < 16; i++) L[i] -= sub;
    }
    int best = 0; double bv = L[0];
    #pragma unroll
    for (int i = 1; i < 16; i++)
        if (L[i] > bv) { bv = L[i]; best = i; }
    return best;
}

// ---------------- diag kernel ----------------
__global__ __launch_bounds__(256, 1) void diag_mma() {
    extern __shared__ __align__(16) char smem[];
    uint32_t sb = smem_u32(smem);
    const int tid = threadIdx.x, wid = tid >> 5, lane = tid & 31;
    const int m0 = blockIdx.x * 128, n0 = blockIdx.y * 256;
    const int wm = (wid & 1) * 64, wn = (wid >> 1) * 64;
    const int gid = lane >> 2, qc = lane & 3;

    GEMM_MAINLOOP(g_xc + (size_t)m0 * KC, g_wc + (size_t)n0 * KC)

    #pragma unroll
    for (int fm = 0; fm < 4; fm++)
        #pragma unroll
        for (int fn = 0; fn < 8; fn++) {
            int mm = m0 + wm + fm * 16 + gid;
            int tcol = (n0 + wn + fn * 8 + 2 * qc) >> 1;
            float* c = acc[fm][fn];
            float s0 = 1.0f / (1.0f + expf(-c[1]));
            float s1 = 1.0f / (1.0f + expf(-c[3]));
            g_dv[(size_t)mm * DM + tcol]       = s0 * tanhf(c[0]);
            g_dv[(size_t)(mm + 8) * DM + tcol] = s1 * tanhf(c[2]);
        }
}

// ---------------- perm kernel ----------------
__global__ __launch_bounds__(256, 1) void perm_mma(const float* __restrict__ h,
                                                   float* __restrict__ out) {
    extern __shared__ __align__(16) char smem[];
    uint32_t sb = smem_u32(smem);
    const int tid = threadIdx.x, wid = tid >> 5, lane = tid & 31;
    const int m0 = blockIdx.x * 128, r = blockIdx.y;
    const int wm = (wid & 1) * 64, wn = (wid >> 1) * 64;
    const int gid = lane >> 2, qc = lane & 3;

    GEMM_MAINLOOP(g_xc + (size_t)m0 * KC, g_wpc + (size_t)r * 256 * KC)

    // stage logits in smem (reusing tile buffers)
    float* Csm = (float*)smem;
    #pragma unroll
    for (int fm = 0; fm < 4; fm++)
        #pragma unroll
        for (int fn = 0; fn < 8; fn++) {
            int mm = wm + fm * 16 + gid, nn = wn + fn * 8 + 2 * qc;
            float* c = acc[fm][fn];
            Csm[mm * CSTR + nn]           = c[0];
            Csm[mm * CSTR + nn + 1]       = c[1];
            Csm[(mm + 8) * CSTR + nn]     = c[2];
            Csm[(mm + 8) * CSTR + nn + 1] = c[3];
        }
    __syncthreads();

    // ---- sinkhorn + argmax (+ exact recompute on near-ties) + permute ----
    const int j = lane & 15, gb = (lane >> 4) << 4;
    const unsigned FULL = 0xffffffffu;

    #pragma unroll 1
    for (int pass = 0; pass < 8; pass++) {
        int m = pass * 16 + (tid >> 4);
        float la[16];
        #pragma unroll
        for (int i = 0; i < 16; i++)
            la[i] = 2.0f * Csm[m * CSTR + i * 16 + j];   // /TAU (TAU=0.5)

        #pragma unroll 1
        for (int it = 0; it < 5; it++) {
            #pragma unroll
            for (int i = 0; i < 16; i++) {
                float mx = la[i];
                mx = fmaxf(mx, __shfl_xor_sync(FULL, mx, 1));
                mx = fmaxf(mx, __shfl_xor_sync(FULL, mx, 2));
                mx = fmaxf(mx, __shfl_xor_sync(FULL, mx, 4));
                mx = fmaxf(mx, __shfl_xor_sync(FULL, mx, 8));
                float e = __expf(la[i] - mx);
                e += __shfl_xor_sync(FULL, e, 1);
                e += __shfl_xor_sync(FULL, e, 2);
                e += __shfl_xor_sync(FULL, e, 4);
                e += __shfl_xor_sync(FULL, e, 8);
                la[i] -= mx + __logf(e);
            }
            float mx = la[0];
            #pragma unroll
            for (int i = 1; i < 16; i++) mx = fmaxf(mx, la[i]);
            float ssum = 0.f;
            #pragma unroll
            for (int i = 0; i < 16; i++) ssum += __expf(la[i] - mx);
            float sub = mx + __logf(ssum);
            #pragma unroll
            for (int i = 0; i < 16; i++) la[i] -= sub;
        }

        // argmax + top-2 gap
        int best = 0; float bv = la[0], sv = -1e30f;
        #pragma unroll
        for (int i = 1; i < 16; i++) {
            if (la[i] > bv) { sv = bv; bv = la[i]; best = i; }
            else if (la[i] > sv) sv = la[i];
        }

        int bg = m0 + m;

        // near-tie guard: recompute exactly (rare)
        if (__any_sync(FULL, (bv - sv) < TIE_EPS))
            best = exact_argmax(bg, r, j);

        float hv = h[(size_t)bg * DM + r * 16 + j];
        float hp = 0.f;
        #pragma unroll
        for (int jj = 0; jj < 16; jj++) {
            int   ib = __shfl_sync(FULL, best, gb + jj);
            float hj = __shfl_sync(FULL, hv,   gb + jj);
            if (ib == j) hp += hj;
        }
        int oi = bg * DM + r * 16 + j;
        out[oi] = g_dv[oi] * hp;
    }
}

// ---------------- launch ----------------
extern "C" void kernel_launch(void* const* d_in, const int* in_sizes, int n_in,
                              void* d_out, int out_size) {
    const float* x  = (const float*)d_in[0];
    const float* h  = (const float*)d_in[1];
    const float* Wp = (const float*)d_in[2];
    const float* Wd = (const float*)d_in[3];
    const float* Wa = (const float*)d_in[4];
    float* out = (float*)d_out;

    const int PSMEM = 128 * CSTR * 4;            // 131584 (> 2*STG)
    const int DSMEM = 2 * STG;                   // 110592
    cudaFuncSetAttribute(perm_mma, cudaFuncAttributeMaxDynamicSharedMemorySize, PSMEM);
    cudaFuncSetAttribute(diag_mma, cudaFuncAttributeMaxDynamicSharedMemorySize, DSMEM);

    conv_x<<<BATCH * DM / 256, 256>>>(x);
    tr_wp<<<dim3(512, 32), dim3(32, 8)>>>(Wp);
    tr_wc<<<dim3(32, 32), dim3(32, 8)>>>(Wd, Wa);
    diag_mma<<<dim3(16, 8), 256, DSMEM>>>();
    perm_mma<<<dim3(16, 64), 256, PSMEM>>>(h, out);
}

// round 5
// speedup vs baseline: 1.1687x; 1.1687x over previous
#include <cuda_runtime.h>
#include <cstdint>
#include <math.h>

#define BATCH 2048
#define DM    1024
#define RNUM  64
#define KC    3072
#define KT    32
#define NKT   (KC / KT)     // 96
#define CSTR  257
#define TIE_EPS 4e-5f
#define MAXF  8192

// perm: 512 threads, tile 256x256, 3 stages
#define STG_P 73728
// diag: 256 threads, tile 128x256, 3 stages
#define STG_D 55296
#define ASZ_D 18432
#define ASZ_P 36864

// ---------------- device scratch ----------------
__device__ float g_dv[BATCH * DM];
__device__ float g_xc[BATCH * KC];          // [xh | xh | xl], k-permuted per 16
__device__ float g_wpc[RNUM * 256 * KC];    // W_perm^T: [Wh | Wl | Wh]
__device__ float g_wc[2 * DM * KC];         // interleaved (d,a) of [Wd|Wa]^T
__device__ int   g_cnt;
__device__ int2  g_flags[MAXF];

// ---------------- helpers ----------------
__device__ __forceinline__ uint32_t smem_u32(const void* p) {
    uint32_t a;
    asm("{ .reg .u64 t; cvta.to.shared.u64 t, %1; cvt.u32.u64 %0, t; }" : "=r"(a) : "l"(p));
    return a;
}
__device__ __forceinline__ float f2tf32(float x) {
    uint32_t r; asm("cvt.rna.tf32.f32 %0, %1;" : "=r"(r) : "f"(x));
    return __uint_as_float(r);
}
__device__ __forceinline__ int p16(int k) {
    return (k & ~15) | ((k & 3) << 2) | ((k >> 2) & 3);
}
__device__ __forceinline__ float4 ldsf4(uint32_t a) {
    float4 r;
    asm volatile("ld.shared.v4.f32 {%0,%1,%2,%3}, [%4];"
                 : "=f"(r.x), "=f"(r.y), "=f"(r.z), "=f"(r.w) : "r"(a));
    return r;
}
#define CPA16(dst, src) asm volatile("cp.async.cg.shared.global [%0], [%1], 16;" :: "r"(dst), "l"(src))
#define CP_COMMIT() asm volatile("cp.async.commit_group;" ::: "memory")
#define CP_WAIT(N)  asm volatile("cp.async.wait_group %0;" :: "n"(N) : "memory")

#define MMA_TF32(c, a0, a1, a2, a3, b0, b1) \
    asm volatile("mma.sync.aligned.m16n8k8.row.col.f32.tf32.tf32.f32 " \
        "{%0,%1,%2,%3}, {%4,%5,%6,%7}, {%8,%9}, {%0,%1,%2,%3};" \
        : "+f"((c)[0]), "+f"((c)[1]), "+f"((c)[2]), "+f"((c)[3]) \
        : "r"(__float_as_uint(a0)), "r"(__float_as_uint(a1)), \
          "r"(__float_as_uint(a2)), "r"(__float_as_uint(a3)), \
          "r"(__float_as_uint(b0)), "r"(__float_as_uint(b1)))

// ---------------- prep kernels ----------------
__global__ void conv_x(const float* __restrict__ x) {
    int g = blockIdx.x * 256 + threadIdx.x;
    if (g == 0) g_cnt = 0;
    int m = g >> 10, k = g & 1023;
    float v = x[g];
    float hi = f2tf32(v);
    size_t b = (size_t)m * KC + p16(k);
    g_xc[b]        = hi;
    g_xc[b + 1024] = hi;
    g_xc[b + 2048] = v - hi;
}

__global__ void tr_wp(const float* __restrict__ Wp) {
    __shared__ float t[32][33];
    int n0 = blockIdx.x * 32, k0 = blockIdx.y * 32;
    int tx = threadIdx.x, ty = threadIdx.y;
    #pragma unroll
    for (int i = 0; i < 4; i++)
        t[ty + i * 8][tx] = Wp[(size_t)(k0 + ty + i * 8) * (RNUM * 256) + n0 + tx];
    __syncthreads();
    #pragma unroll
    for (int i = 0; i < 4; i++) {
        int rr = ty + i * 8;
        float v = t[tx][rr];
        float hi = f2tf32(v);
        int p = p16(k0 + tx);
        size_t b = (size_t)(n0 + rr) * KC;
        g_wpc[b + p]        = hi;
        g_wpc[b + 1024 + p] = v - hi;
        g_wpc[b + 2048 + p] = hi;
    }
}

__global__ void tr_wc(const float* __restrict__ Wd, const float* __restrict__ Wa) {
    __shared__ float t[2][32][33];
    int n0 = blockIdx.x * 32, k0 = blockIdx.y * 32;
    int tx = threadIdx.x, ty = threadIdx.y;
    #pragma unroll
    for (int i = 0; i < 4; i++) {
        int rr = ty + i * 8;
        t[0][rr][tx] = Wd[(size_t)(k0 + rr) * DM + n0 + tx];
        t[1][rr][tx] = Wa[(size_t)(k0 + rr) * DM + n0 + tx];
    }
    __syncthreads();
    #pragma unroll
    for (int i = 0; i < 4; i++) {
        int rr = ty + i * 8;
        int p = p16(k0 + tx);
        #pragma unroll
        for (int s = 0; s < 2; s++) {
            float v = t[s][tx][rr];
            float hi = f2tf32(v);
            size_t b = (size_t)(2 * (n0 + rr) + s) * KC;
            g_wc[b + p]        = hi;
            g_wc[b + 1024 + p] = v - hi;
            g_wc[b + 2048 + p] = hi;
        }
    }
}

// ---------------- GEMM building blocks ----------------
__device__ __forceinline__ void ld_tile_d(uint32_t sA, uint32_t sB,
                                          const float* Ag, const float* Bg,
                                          int gk, int tid) {
    #pragma unroll
    for (int i = 0; i < 4; i++) {
        int v = tid + i * 256, row = v >> 3, c = v & 7;
        CPA16(sA + row * 144 + c * 16, (const char*)(Ag + (size_t)row * KC + gk) + c * 16);
    }
    #pragma unroll
    for (int i = 0; i < 8; i++) {
        int v = tid + i * 256, row = v >> 3, c = v & 7;
        CPA16(sB + row * 144 + c * 16, (const char*)(Bg + (size_t)row * KC + gk) + c * 16);
    }
}

__device__ __forceinline__ void ld_tile_p(uint32_t sA, uint32_t sB,
                                          const float* Ag, const float* Bg,
                                          int gk, int tid) {
    #pragma unroll
    for (int i = 0; i < 4; i++) {
        int v = tid + i * 512, row = v >> 3, c = v & 7;
        CPA16(sA + row * 144 + c * 16, (const char*)(Ag + (size_t)row * KC + gk) + c * 16);
    }
    #pragma unroll
    for (int i = 0; i < 4; i++) {
        int v = tid + i * 512, row = v >> 3, c = v & 7;
        CPA16(sB + row * 144 + c * 16, (const char*)(Bg + (size_t)row * KC + gk) + c * 16);
    }
}

__device__ __forceinline__ void compute_tile(uint32_t sA, uint32_t sB,
                                             int wm, int wn, int gid, int qc,
                                             float acc[4][8][4]) {
    #pragma unroll
    for (int g16 = 0; g16 < 2; g16++) {
        float4 alo[4], ahi[4], bb[8];
        uint32_t coff = (g16 * 4 + qc) * 16;
        #pragma unroll
        for (int fm = 0; fm < 4; fm++) {
            uint32_t a = sA + (wm + fm * 16 + gid) * 144 + coff;
            alo[fm] = ldsf4(a);
            ahi[fm] = ldsf4(a + 8 * 144);
        }
        #pragma unroll
        for (int fn = 0; fn < 8; fn++)
            bb[fn] = ldsf4(sB + (wn + fn * 8 + gid) * 144 + coff);
        #pragma unroll
        for (int fm = 0; fm < 4; fm++)
            #pragma unroll
            for (int fn = 0; fn < 8; fn++) {
                MMA_TF32(acc[fm][fn], alo[fm].x, ahi[fm].x, alo[fm].y, ahi[fm].y,
                         bb[fn].x, bb[fn].y);
                MMA_TF32(acc[fm][fn], alo[fm].z, ahi[fm].z, alo[fm].w, ahi[fm].w,
                         bb[fn].z, bb[fn].w);
            }
    }
}

// 3-stage mainloop, one barrier per k-tile (prefetch distance 2)
#define GEMM_MAINLOOP(LD, STG, ASZ, Ag, Bg)                                     \
    float acc[4][8][4] = {};                                                    \
    LD(sb, sb + ASZ, Ag, Bg, 0, tid); CP_COMMIT();                              \
    LD(sb + STG, sb + STG + ASZ, Ag, Bg, KT, tid); CP_COMMIT();                 \
    for (int kt = 0; kt < NKT; kt++) {                                          \
        if (kt + 1 < NKT) { CP_WAIT(1); } else { CP_WAIT(0); }                  \
        __syncthreads();                                                        \
        if (kt + 2 < NKT) {                                                     \
            uint32_t pb = sb + ((kt + 2) % 3) * STG;                            \
            LD(pb, pb + ASZ, Ag, Bg, (kt + 2) * KT, tid); CP_COMMIT();          \
        }                                                                       \
        uint32_t st = sb + (kt % 3) * STG;                                      \
        compute_tile(st, st + ASZ, wm, wn, gid, qc, acc);                       \
    }                                                                           \
    __syncthreads();

// ---------------- diag kernel (256 thr, 128x256) ----------------
__global__ __launch_bounds__(256, 1) void diag_mma() {
    extern __shared__ __align__(16) char smem[];
    uint32_t sb = smem_u32(smem);
    const int tid = threadIdx.x, wid = tid >> 5, lane = tid & 31;
    const int m0 = blockIdx.x * 128, n0 = blockIdx.y * 256;
    const int wm = (wid & 1) * 64, wn = (wid >> 1) * 64;
    const int gid = lane >> 2, qc = lane & 3;

    GEMM_MAINLOOP(ld_tile_d, STG_D, ASZ_D, g_xc + (size_t)m0 * KC, g_wc + (size_t)n0 * KC)

    #pragma unroll
    for (int fm = 0; fm < 4; fm++)
        #pragma unroll
        for (int fn = 0; fn < 8; fn++) {
            int mm = m0 + wm + fm * 16 + gid;
            int tcol = (n0 + wn + fn * 8 + 2 * qc) >> 1;
            float* c = acc[fm][fn];
            float s0 = 1.0f / (1.0f + expf(-c[1]));
            float s1 = 1.0f / (1.0f + expf(-c[3]));
            g_dv[(size_t)mm * DM + tcol]       = s0 * tanhf(c[0]);
            g_dv[(size_t)(mm + 8) * DM + tcol] = s1 * tanhf(c[2]);
        }
}

// ---------------- perm kernel (512 thr, 256x256) ----------------
__global__ __launch_bounds__(512, 1) void perm_mma(const float* __restrict__ h,
                                                   float* __restrict__ out) {
    extern __shared__ __align__(16) char smem[];
    uint32_t sb = smem_u32(smem);
    const int tid = threadIdx.x, wid = tid >> 5, lane = tid & 31;
    const int m0 = blockIdx.x * 256, r = blockIdx.y;
    const int wm = (wid & 3) * 64, wn = (wid >> 2) * 64;
    const int gid = lane >> 2, qc = lane & 3;

    GEMM_MAINLOOP(ld_tile_p, STG_P, ASZ_P, g_xc + (size_t)m0 * KC,
                  g_wpc + (size_t)r * 256 * KC)

    float* Csm = (float*)smem;
    const int j = lane & 15, gb = (lane >> 4) << 4;
    const unsigned FULL = 0xffffffffu;

    #pragma unroll 1
    for (int mh = 0; mh < 2; mh++) {
        // stage this half's logits
        if ((wm >> 7) == mh) {
            #pragma unroll
            for (int fm = 0; fm < 4; fm++)
                #pragma unroll
                for (int fn = 0; fn < 8; fn++) {
                    int mml = (wm & 127) + fm * 16 + gid, nn = wn + fn * 8 + 2 * qc;
                    float* c = acc[fm][fn];
                    Csm[mml * CSTR + nn]           = c[0];
                    Csm[mml * CSTR + nn + 1]       = c[1];
                    Csm[(mml + 8) * CSTR + nn]     = c[2];
                    Csm[(mml + 8) * CSTR + nn + 1] = c[3];
                }
        }
        __syncthreads();

        #pragma unroll 1
        for (int pass = 0; pass < 4; pass++) {
            int ml = pass * 32 + wid * 2 + (lane >> 4);
            float la[16];
            #pragma unroll
            for (int i = 0; i < 16; i++)
                la[i] = 2.0f * Csm[ml * CSTR + i * 16 + j];   // /TAU

            #pragma unroll 1
            for (int it = 0; it < 5; it++) {
                #pragma unroll
                for (int i = 0; i < 16; i++) {
                    float mx = la[i];
                    mx = fmaxf(mx, __shfl_xor_sync(FULL, mx, 1));
                    mx = fmaxf(mx, __shfl_xor_sync(FULL, mx, 2));
                    mx = fmaxf(mx, __shfl_xor_sync(FULL, mx, 4));
                    mx = fmaxf(mx, __shfl_xor_sync(FULL, mx, 8));
                    float e = __expf(la[i] - mx);
                    e += __shfl_xor_sync(FULL, e, 1);
                    e += __shfl_xor_sync(FULL, e, 2);
                    e += __shfl_xor_sync(FULL, e, 4);
                    e += __shfl_xor_sync(FULL, e, 8);
                    la[i] -= mx + __logf(e);
                }
                if (it < 4) {   // final col-norm is argmax-invariant: skip
                    float mx = la[0];
                    #pragma unroll
                    for (int i = 1; i < 16; i++) mx = fmaxf(mx, la[i]);
                    float ssum = 0.f;
                    #pragma unroll
                    for (int i = 0; i < 16; i++) ssum += __expf(la[i] - mx);
                    float sub = mx + __logf(ssum);
                    #pragma unroll
                    for (int i = 0; i < 16; i++) la[i] -= sub;
                }
            }

            int best = 0; float bv = la[0], sv = -1e30f;
            #pragma unroll
            for (int i = 1; i < 16; i++) {
                if (la[i] > bv) { sv = bv; bv = la[i]; best = i; }
                else if (la[i] > sv) sv = la[i];
            }

            int bg = m0 + mh * 128 + ml;

            // flag near-tie block (per 16-lane half) for exact fixup
            unsigned bal = __ballot_sync(FULL, (bv - sv) < TIE_EPS);
            if (((bal >> gb) & 0xFFFFu) && lane == gb) {
                int idx = atomicAdd(&g_cnt, 1);
                if (idx < MAXF) g_flags[idx] = make_int2(bg, r);
            }

            float hv = h[(size_t)bg * DM + r * 16 + j];
            float hp = 0.f;
            #pragma unroll
            for (int jj = 0; jj < 16; jj++) {
                int   ib = __shfl_sync(FULL, best, gb + jj);
                float hj = __shfl_sync(FULL, hv,   gb + jj);
                if (ib == j) hp += hj;
            }
            int oi = bg * DM + r * 16 + j;
            out[oi] = g_dv[oi] * hp;
        }
        __syncthreads();
    }
}

// ---------------- exact fixup (rare near-tie blocks) ----------------
__global__ void fixup(const float* __restrict__ h, float* __restrict__ out) {
    __shared__ float xs[1024];
    __shared__ double Ls[256];
    int n = g_cnt; if (n > MAXF) n = MAXF;
    const int tid = threadIdx.x;

    for (int f = blockIdx.x; f < n; f += gridDim.x) {
        int bg = g_flags[f].x, r = g_flags[f].y;
        for (int k = tid; k < 1024; k += 256)
            xs[k] = g_xc[(size_t)bg * KC + k] + g_xc[(size_t)bg * KC + 2048 + k];
        __syncthreads();

        {   // one exact dot per thread: row i = tid>>4, col j = tid&15
            const float* wr = g_wpc + ((size_t)r * 256 + (tid >> 4) * 16 + (tid & 15)) * KC;
            double s = 0.0;
            #pragma unroll 1
            for (int k = 0; k < 1024; k += 4) {
                float4 hi4 = *(const float4*)(wr + k);
                float4 lo4 = *(const float4*)(wr + 1024 + k);
                s += (double)xs[k + 0] * ((double)hi4.x + (double)lo4.x);
                s += (double)xs[k + 1] * ((double)hi4.y + (double)lo4.y);
                s += (double)xs[k + 2] * ((double)hi4.z + (double)lo4.z);
                s += (double)xs[k + 3] * ((double)hi4.w + (double)lo4.w);
            }
            Ls[tid] = 2.0 * s;
        }
        __syncthreads();

        if (tid < 16) {
            const unsigned M16 = 0xFFFFu;
            int j = tid;
            double L[16];
            #pragma unroll
            for (int i = 0; i < 16; i++) L[i] = Ls[i * 16 + j];
            #pragma unroll 1
            for (int it = 0; it < 5; it++) {
                #pragma unroll 1
                for (int i = 0; i < 16; i++) {
                    double mx = L[i];
                    mx = fmax(mx, __shfl_xor_sync(M16, mx, 1));
                    mx = fmax(mx, __shfl_xor_sync(M16, mx, 2));
                    mx = fmax(mx, __shfl_xor_sync(M16, mx, 4));
                    mx = fmax(mx, __shfl_xor_sync(M16, mx, 8));
                    double e = exp(L[i] - mx);
                    e += __shfl_xor_sync(M16, e, 1);
                    e += __shfl_xor_sync(M16, e, 2);
                    e += __shfl_xor_sync(M16, e, 4);
                    e += __shfl_xor_sync(M16, e, 8);
                    L[i] -= mx + log(e);
                }
                if (it < 4) {
                    double mx = L[0];
                    #pragma unroll
                    for (int i = 1; i < 16; i++) mx = fmax(mx, L[i]);
                    double ss = 0.0;
                    #pragma unroll
                    for (int i = 0; i < 16; i++) ss += exp(L[i] - mx);
                    double sub = mx + log(ss);
                    #pragma unroll
                    for (int i = 0; i < 16; i++) L[i] -= sub;
                }
            }
            int best = 0; double bv = L[0];
            #pragma unroll
            for (int i = 1; i < 16; i++)
                if (L[i] > bv) { bv = L[i]; best = i; }

            float hv = h[(size_t)bg * DM + r * 16 + j];
            float hp = 0.f;
            #pragma unroll
            for (int jj = 0; jj < 16; jj++) {
                int   ib = __shfl_sync(M16, best, jj);
                float hj = __shfl_sync(M16, hv,   jj);
                if (ib == j) hp += hj;
            }
            int oi = bg * DM + r * 16 + j;
            out[oi] = g_dv[oi] * hp;
        }
        __syncthreads();
    }
}

// ---------------- launch ----------------
extern "C" void kernel_launch(void* const* d_in, const int* in_sizes, int n_in,
                              void* d_out, int out_size) {
    const float* x  = (const float*)d_in[0];
    const float* h  = (const float*)d_in[1];
    const float* Wp = (const float*)d_in[2];
    const float* Wd = (const float*)d_in[3];
    const float* Wa = (const float*)d_in[4];
    float* out = (float*)d_out;

    const int PSMEM = 3 * STG_P;   // 221184
    const int DSMEM = 3 * STG_D;   // 165888
    cudaFuncSetAttribute(perm_mma, cudaFuncAttributeMaxDynamicSharedMemorySize, PSMEM);
    cudaFuncSetAttribute(diag_mma, cudaFuncAttributeMaxDynamicSharedMemorySize, DSMEM);

    conv_x<<<BATCH * DM / 256, 256>>>(x);
    tr_wp<<<dim3(512, 32), dim3(32, 8)>>>(Wp);
    tr_wc<<<dim3(32, 32), dim3(32, 8)>>>(Wd, Wa);
    diag_mma<<<dim3(16, 8), 256, DSMEM>>>();
    perm_mma<<<dim3(8, 64), 512, PSMEM>>>(h, out);
    fixup<<<256, 256>>>(h, out);
}

// round 6
// speedup vs baseline: 2.2758x; 1.9472x over previous
#include <cuda_runtime.h>
#include <cuda_fp16.h>
#include <cstdint>
#include <math.h>

#define BATCH 2048
#define DM    1024
#define RNUM  64
#define KH    3072          // concat K in halfs
#define KT    64            // k-tile in halfs (128 B rows)
#define NKT   (KH / KT)     // 48
#define RSTR  160           // smem row stride bytes
#define STG   61440         // (128+256)*160
#define ASZ   20480         // 128*160
#define CSTR  257
#define TIE_EPS 1e-4f
#define MAXF  8192
#define SMEMSZ (3 * STG)

// ---------------- device scratch ----------------
__device__ float  g_dv[BATCH * DM];
__device__ __half g_xc[BATCH * KH];           // A slices [xh | xh/2048 | xl*2048]
__device__ __half g_wpc[RNUM * 256 * KH];     // W_perm^T slices [Wh | Wl*2048 | Wh/2048]
__device__ __half g_wc[2 * DM * KH];          // interleaved (d,a) of [Wd|Wa]^T, same slices
__device__ int    g_cnt;
__device__ int2   g_flags[MAXF];

// ---------------- helpers ----------------
__device__ __forceinline__ uint32_t smem_u32(const void* p) {
    uint32_t a;
    asm("{ .reg .u64 t; cvta.to.shared.u64 t, %1; cvt.u32.u64 %0, t; }" : "=r"(a) : "l"(p));
    return a;
}
// k-permutation within 16-groups: logical k -> stored slot, making each lane's
// mma fragment halves contiguous: slots [0,1,8,9 | 2,3,10,11 | 4,5,12,13 | 6,7,14,15]
__device__ __forceinline__ int sp16(int k) {
    return (k & ~15) | ((k & 6) << 1) | ((k & 8) >> 2) | (k & 1);
}
__device__ __forceinline__ void lds64(uint32_t& r0, uint32_t& r1, uint32_t a) {
    asm volatile("ld.shared.v2.b32 {%0,%1}, [%2];" : "=r"(r0), "=r"(r1) : "r"(a));
}
#define CPA16(dst, src) asm volatile("cp.async.cg.shared.global [%0], [%1], 16;" :: "r"(dst), "l"(src))
#define CP_COMMIT() asm volatile("cp.async.commit_group;" ::: "memory")
#define CP_WAIT(N)  asm volatile("cp.async.wait_group %0;" :: "n"(N) : "memory")

#define MMA_F16(c, a0, a1, a2, a3, b0, b1) \
    asm volatile("mma.sync.aligned.m16n8k16.row.col.f32.f16.f16.f32 " \
        "{%0,%1,%2,%3}, {%4,%5,%6,%7}, {%8,%9}, {%0,%1,%2,%3};" \
        : "+f"((c)[0]), "+f"((c)[1]), "+f"((c)[2]), "+f"((c)[3]) \
        : "r"(a0), "r"(a1), "r"(a2), "r"(a3), "r"(b0), "r"(b1))

// ---------------- prep kernels ----------------
__global__ void conv_x(const float* __restrict__ x) {
    int g = blockIdx.x * 256 + threadIdx.x;
    if (g == 0) g_cnt = 0;
    int m = g >> 10, k = g & 1023;
    float v = x[g];
    __half hh = __float2half_rn(v);
    float hf = __half2float(hh);
    size_t b = (size_t)m * KH + sp16(k);
    g_xc[b]        = hh;
    g_xc[b + 1024] = __float2half_rn(hf * (1.0f / 2048.0f));
    g_xc[b + 2048] = __float2half_rn((v - hf) * 2048.0f);
}

__global__ void tr_wp(const float* __restrict__ Wp) {
    __shared__ float t[32][33];
    int n0 = blockIdx.x * 32, k0 = blockIdx.y * 32;
    int tx = threadIdx.x, ty = threadIdx.y;
    #pragma unroll
    for (int i = 0; i < 4; i++)
        t[ty + i * 8][tx] = Wp[(size_t)(k0 + ty + i * 8) * (RNUM * 256) + n0 + tx];
    __syncthreads();
    #pragma unroll
    for (int i = 0; i < 4; i++) {
        int rr = ty + i * 8;
        float v = t[tx][rr];
        __half hh = __float2half_rn(v);
        float hf = __half2float(hh);
        int p = sp16(k0 + tx);
        size_t b = (size_t)(n0 + rr) * KH;
        g_wpc[b + p]        = hh;
        g_wpc[b + 1024 + p] = __float2half_rn((v - hf) * 2048.0f);
        g_wpc[b + 2048 + p] = __float2half_rn(hf * (1.0f / 2048.0f));
    }
}

__global__ void tr_wc(const float* __restrict__ Wd, const float* __restrict__ Wa) {
    __shared__ float t[2][32][33];
    int n0 = blockIdx.x * 32, k0 = blockIdx.y * 32;
    int tx = threadIdx.x, ty = threadIdx.y;
    #pragma unroll
    for (int i = 0; i < 4; i++) {
        int rr = ty + i * 8;
        t[0][rr][tx] = Wd[(size_t)(k0 + rr) * DM + n0 + tx];
        t[1][rr][tx] = Wa[(size_t)(k0 + rr) * DM + n0 + tx];
    }
    __syncthreads();
    #pragma unroll
    for (int i = 0; i < 4; i++) {
        int rr = ty + i * 8;
        int p = sp16(k0 + tx);
        #pragma unroll
        for (int s = 0; s < 2; s++) {
            float v = t[s][tx][rr];
            __half hh = __float2half_rn(v);
            float hf = __half2float(hh);
            size_t b = (size_t)(2 * (n0 + rr) + s) * KH;
            g_wc[b + p]        = hh;
            g_wc[b + 1024 + p] = __float2half_rn((v - hf) * 2048.0f);
            g_wc[b + 2048 + p] = __float2half_rn(hf * (1.0f / 2048.0f));
        }
    }
}

// ---------------- GEMM building blocks ----------------
__device__ __forceinline__ void ld_tile(uint32_t sA, uint32_t sB,
                                        const __half* Ag, const __half* Bg,
                                        int gk, int tid) {
    #pragma unroll
    for (int i = 0; i < 4; i++) {                 // A: 128 rows x 8 x 16B
        int v = tid + i * 256, row = v >> 3, c = v & 7;
        CPA16(sA + row * RSTR + c * 16, (const char*)(Ag + (size_t)row * KH + gk) + c * 16);
    }
    #pragma unroll
    for (int i = 0; i < 8; i++) {                 // B: 256 rows x 8 x 16B
        int v = tid + i * 256, row = v >> 3, c = v & 7;
        CPA16(sB + row * RSTR + c * 16, (const char*)(Bg + (size_t)row * KH + gk) + c * 16);
    }
}

__device__ __forceinline__ void compute_tile(uint32_t sA, uint32_t sB,
                                             int wm, int wn, int gid, int qc,
                                             float acc[4][8][4]) {
    #pragma unroll
    for (int ks = 0; ks < 4; ks++) {
        uint32_t coff = ks * 32 + qc * 8;
        uint32_t A0[4], A1[4], A2[4], A3[4], B0[8], B1[8];
        #pragma unroll
        for (int fm = 0; fm < 4; fm++) {
            uint32_t a = sA + (wm + fm * 16 + gid) * RSTR + coff;
            lds64(A0[fm], A2[fm], a);
            lds64(A1[fm], A3[fm], a + 8 * RSTR);
        }
        #pragma unroll
        for (int fn = 0; fn < 8; fn++)
            lds64(B0[fn], B1[fn], sB + (wn + fn * 8 + gid) * RSTR + coff);
        #pragma unroll
        for (int fm = 0; fm < 4; fm++)
            #pragma unroll
            for (int fn = 0; fn < 8; fn++)
                MMA_F16(acc[fm][fn], A0[fm], A1[fm], A2[fm], A3[fm], B0[fn], B1[fn]);
    }
}

// 3-stage mainloop, one barrier per k-tile (prefetch distance 2)
#define GEMM_MAINLOOP(Ag, Bg)                                                   \
    float acc[4][8][4] = {};                                                    \
    ld_tile(sb, sb + ASZ, Ag, Bg, 0, tid); CP_COMMIT();                         \
    ld_tile(sb + STG, sb + STG + ASZ, Ag, Bg, KT, tid); CP_COMMIT();            \
    for (int kt = 0; kt < NKT; kt++) {                                          \
        if (kt + 1 < NKT) { CP_WAIT(1); } else { CP_WAIT(0); }                  \
        __syncthreads();                                                        \
        if (kt + 2 < NKT) {                                                     \
            uint32_t pb = sb + ((kt + 2) % 3) * STG;                            \
            ld_tile(pb, pb + ASZ, Ag, Bg, (kt + 2) * KT, tid); CP_COMMIT();     \
        }                                                                       \
        uint32_t st = sb + (kt % 3) * STG;                                      \
        compute_tile(st, st + ASZ, wm, wn, gid, qc, acc);                       \
    }                                                                           \
    __syncthreads();

// ---------------- diag kernel (256 thr, 128x256) ----------------
__global__ __launch_bounds__(256, 1) void diag_mma() {
    extern __shared__ __align__(16) char smem[];
    uint32_t sb = smem_u32(smem);
    const int tid = threadIdx.x, wid = tid >> 5, lane = tid & 31;
    const int m0 = blockIdx.x * 128, n0 = blockIdx.y * 256;
    const int wm = (wid & 1) * 64, wn = (wid >> 1) * 64;
    const int gid = lane >> 2, qc = lane & 3;

    GEMM_MAINLOOP(g_xc + (size_t)m0 * KH, g_wc + (size_t)n0 * KH)

    #pragma unroll
    for (int fm = 0; fm < 4; fm++)
        #pragma unroll
        for (int fn = 0; fn < 8; fn++) {
            int mm = m0 + wm + fm * 16 + gid;
            int tcol = (n0 + wn + fn * 8 + 2 * qc) >> 1;
            float* c = acc[fm][fn];
            float s0 = 1.0f / (1.0f + expf(-c[1]));
            float s1 = 1.0f / (1.0f + expf(-c[3]));
            g_dv[(size_t)mm * DM + tcol]       = s0 * tanhf(c[0]);
            g_dv[(size_t)(mm + 8) * DM + tcol] = s1 * tanhf(c[2]);
        }
}

// ---------------- perm kernel (256 thr, 128x256) ----------------
__global__ __launch_bounds__(256, 1) void perm_mma(const float* __restrict__ h,
                                                   float* __restrict__ out) {
    extern __shared__ __align__(16) char smem[];
    uint32_t sb = smem_u32(smem);
    const int tid = threadIdx.x, wid = tid >> 5, lane = tid & 31;
    const int m0 = blockIdx.x * 128, r = blockIdx.y;
    const int wm = (wid & 1) * 64, wn = (wid >> 1) * 64;
    const int gid = lane >> 2, qc = lane & 3;

    GEMM_MAINLOOP(g_xc + (size_t)m0 * KH, g_wpc + (size_t)r * 256 * KH)

    // stage logits into smem (reuse tile buffers)
    float* Csm = (float*)smem;
    #pragma unroll
    for (int fm = 0; fm < 4; fm++)
        #pragma unroll
        for (int fn = 0; fn < 8; fn++) {
            int mm = wm + fm * 16 + gid, nn = wn + fn * 8 + 2 * qc;
            float* c = acc[fm][fn];
            Csm[mm * CSTR + nn]           = c[0];
            Csm[mm * CSTR + nn + 1]       = c[1];
            Csm[(mm + 8) * CSTR + nn]     = c[2];
            Csm[(mm + 8) * CSTR + nn + 1] = c[3];
        }
    __syncthreads();

    // ---- sinkhorn + argmax (+ near-tie flag) + permute ----
    const int j = lane & 15, gb = (lane >> 4) << 4;
    const unsigned FULL = 0xffffffffu;

    #pragma unroll 1
    for (int pass = 0; pass < 8; pass++) {
        int m = pass * 16 + (tid >> 4);
        float la[16];
        #pragma unroll
        for (int i = 0; i < 16; i++)
            la[i] = 2.0f * Csm[m * CSTR + i * 16 + j];   // /TAU (TAU=0.5)

        #pragma unroll 1
        for (int it = 0; it < 5; it++) {
            #pragma unroll
            for (int i = 0; i < 16; i++) {
                float mx = la[i];
                mx = fmaxf(mx, __shfl_xor_sync(FULL, mx, 1));
                mx = fmaxf(mx, __shfl_xor_sync(FULL, mx, 2));
                mx = fmaxf(mx, __shfl_xor_sync(FULL, mx, 4));
                mx = fmaxf(mx, __shfl_xor_sync(FULL, mx, 8));
                float e = __expf(la[i] - mx);
                e += __shfl_xor_sync(FULL, e, 1);
                e += __shfl_xor_sync(FULL, e, 2);
                e += __shfl_xor_sync(FULL, e, 4);
                e += __shfl_xor_sync(FULL, e, 8);
                la[i] -= mx + __logf(e);
            }
            if (it < 4) {   // final col-norm is argmax-invariant: skip
                float mx = la[0];
                #pragma unroll
                for (int i = 1; i < 16; i++) mx = fmaxf(mx, la[i]);
                float ssum = 0.f;
                #pragma unroll
                for (int i = 0; i < 16; i++) ssum += __expf(la[i] - mx);
                float sub = mx + __logf(ssum);
                #pragma unroll
                for (int i = 0; i < 16; i++) la[i] -= sub;
            }
        }

        int best = 0; float bv = la[0], sv = -1e30f;
        #pragma unroll
        for (int i = 1; i < 16; i++) {
            if (la[i] > bv) { sv = bv; bv = la[i]; best = i; }
            else if (la[i] > sv) sv = la[i];
        }

        int bg = m0 + m;

        unsigned bal = __ballot_sync(FULL, (bv - sv) < TIE_EPS);
        if (((bal >> gb) & 0xFFFFu) && lane == gb) {
            int idx = atomicAdd(&g_cnt, 1);
            if (idx < MAXF) g_flags[idx] = make_int2(bg, r);
        }

        float hv = h[(size_t)bg * DM + r * 16 + j];
        float hp = 0.f;
        #pragma unroll
        for (int jj = 0; jj < 16; jj++) {
            int   ib = __shfl_sync(FULL, best, gb + jj);
            float hj = __shfl_sync(FULL, hv,   gb + jj);
            if (ib == j) hp += hj;
        }
        int oi = bg * DM + r * 16 + j;
        out[oi] = g_dv[oi] * hp;
    }
}

// ---------------- exact fixup from ORIGINAL fp32 inputs (rare) ----------------
__global__ void fixup(const float* __restrict__ x, const float* __restrict__ Wp,
                      const float* __restrict__ h, float* __restrict__ out) {
    __shared__ float xs[1024];
    __shared__ double Ls[256];
    int n = g_cnt; if (n > MAXF) n = MAXF;
    const int tid = threadIdx.x;

    for (int f = blockIdx.x; f < n; f += gridDim.x) {
        int bg = g_flags[f].x, r = g_flags[f].y;
        __syncthreads();
        for (int k = tid; k < 1024; k += 256) xs[k] = x[(size_t)bg * DM + k];
        __syncthreads();

        {
            int col = r * 256 + tid;           // tid = i*16+j over the 16x16 block
            double s = 0.0;
            #pragma unroll 4
            for (int k = 0; k < 1024; k++)
                s += (double)xs[k] * (double)Wp[(size_t)k * (RNUM * 256) + col];
            Ls[tid] = 2.0 * s;
        }
        __syncthreads();

        if (tid < 16) {
            const unsigned M16 = 0xFFFFu;
            int j = tid;
            double L[16];
            #pragma unroll
            for (int i = 0; i < 16; i++) L[i] = Ls[i * 16 + j];
            #pragma unroll 1
            for (int it = 0; it < 5; it++) {
                #pragma unroll 1
                for (int i = 0; i < 16; i++) {
                    double mx = L[i];
                    mx = fmax(mx, __shfl_xor_sync(M16, mx, 1));
                    mx = fmax(mx, __shfl_xor_sync(M16, mx, 2));
                    mx = fmax(mx, __shfl_xor_sync(M16, mx, 4));
                    mx = fmax(mx, __shfl_xor_sync(M16, mx, 8));
                    double e = exp(L[i] - mx);
                    e += __shfl_xor_sync(M16, e, 1);
                    e += __shfl_xor_sync(M16, e, 2);
                    e += __shfl_xor_sync(M16, e, 4);
                    e += __shfl_xor_sync(M16, e, 8);
                    L[i] -= mx + log(e);
                }
                if (it < 4) {
                    double mx = L[0];
                    #pragma unroll
                    for (int i = 1; i < 16; i++) mx = fmax(mx, L[i]);
                    double ss = 0.0;
                    #pragma unroll
                    for (int i = 0; i < 16; i++) ss += exp(L[i] - mx);
                    double sub = mx + log(ss);
                    #pragma unroll
                    for (int i = 0; i < 16; i++) L[i] -= sub;
                }
            }
            int best = 0; double bv = L[0];
            #pragma unroll
            for (int i = 1; i < 16; i++)
                if (L[i] > bv) { bv = L[i]; best = i; }

            float hv = h[(size_t)bg * DM + r * 16 + j];
            float hp = 0.f;
            #pragma unroll
            for (int jj = 0; jj < 16; jj++) {
                int   ib = __shfl_sync(M16, best, jj);
                float hj = __shfl_sync(M16, hv,   jj);
                if (ib == j) hp += hj;
            }
            int oi = bg * DM + r * 16 + j;
            out[oi] = g_dv[oi] * hp;
        }
        __syncthreads();
    }
}

// ---------------- launch ----------------
extern "C" void kernel_launch(void* const* d_in, const int* in_sizes, int n_in,
                              void* d_out, int out_size) {
    const float* x  = (const float*)d_in[0];
    const float* h  = (const float*)d_in[1];
    const float* Wp = (const float*)d_in[2];
    const float* Wd = (const float*)d_in[3];
    const float* Wa = (const float*)d_in[4];
    float* out = (float*)d_out;

    cudaFuncSetAttribute(perm_mma, cudaFuncAttributeMaxDynamicSharedMemorySize, SMEMSZ);
    cudaFuncSetAttribute(diag_mma, cudaFuncAttributeMaxDynamicSharedMemorySize, SMEMSZ);

    conv_x<<<BATCH * DM / 256, 256>>>(x);
    tr_wp<<<dim3(512, 32), dim3(32, 8)>>>(Wp);
    tr_wc<<<dim3(32, 32), dim3(32, 8)>>>(Wd, Wa);
    diag_mma<<<dim3(16, 8), 256, SMEMSZ>>>();
    perm_mma<<<dim3(16, 64), 256, SMEMSZ>>>(h, out);
    fixup<<<128, 256>>>(x, Wp, h, out);
}

// round 7
// speedup vs baseline: 3.6636x; 1.6098x over previous
#include <cuda_runtime.h>
#include <cuda_fp16.h>
#include <cstdint>
#include <math.h>

#define BATCH 2048
#define DM    1024
#define RNUM  64
#define KH    3072          // concat K in halfs
#define KT    64            // k-tile in halfs (128 B rows)
#define NKT   (KH / KT)     // 48
#define RSTR  160           // smem row stride bytes
#define STG   61440         // (128+256)*160
#define ASZ   20480         // 128*160
#define CSTR  257
#define TIE_EPS 3e-5f
#define MAXF  16384
#define SMEMSZ (3 * STG)
#define SC    64.0f         // balanced slice scale (keeps everything fp16-normal)

// ---------------- device scratch ----------------
__device__ float  g_dv[BATCH * DM];
__device__ __half g_xc[BATCH * KH];           // A slices [xh | xh/64 | xl*64]
__device__ __half g_wpc[RNUM * 256 * KH];     // W_perm^T slices [Wh | Wl*64 | Wh/64]
__device__ __half g_wc[2 * DM * KH];          // interleaved (d,a) of [Wd|Wa]^T
__device__ int    g_cnt;
__device__ int2   g_flags[MAXF];

// ---------------- helpers ----------------
__device__ __forceinline__ uint32_t smem_u32(const void* p) {
    uint32_t a;
    asm("{ .reg .u64 t; cvta.to.shared.u64 t, %1; cvt.u32.u64 %0, t; }" : "=r"(a) : "l"(p));
    return a;
}
// k-permutation within 16-groups making each lane's mma fragment halves contiguous
__device__ __forceinline__ int sp16(int k) {
    return (k & ~15) | ((k & 6) << 1) | ((k & 8) >> 2) | (k & 1);
}
__device__ __forceinline__ void lds64(uint32_t& r0, uint32_t& r1, uint32_t a) {
    asm volatile("ld.shared.v2.b32 {%0,%1}, [%2];" : "=r"(r0), "=r"(r1) : "r"(a));
}
#define CPA16(dst, src) asm volatile("cp.async.cg.shared.global [%0], [%1], 16;" :: "r"(dst), "l"(src))
#define CP_COMMIT() asm volatile("cp.async.commit_group;" ::: "memory")
#define CP_WAIT(N)  asm volatile("cp.async.wait_group %0;" :: "n"(N) : "memory")

#define MMA_F16(c, a0, a1, a2, a3, b0, b1) \
    asm volatile("mma.sync.aligned.m16n8k16.row.col.f32.f16.f16.f32 " \
        "{%0,%1,%2,%3}, {%4,%5,%6,%7}, {%8,%9}, {%0,%1,%2,%3};" \
        : "+f"((c)[0]), "+f"((c)[1]), "+f"((c)[2]), "+f"((c)[3]) \
        : "r"(a0), "r"(a1), "r"(a2), "r"(a3), "r"(b0), "r"(b1))

// ---------------- prep kernels ----------------
__global__ void conv_x(const float* __restrict__ x) {
    int g = blockIdx.x * 256 + threadIdx.x;
    if (g == 0) g_cnt = 0;
    int m = g >> 10, k = g & 1023;
    float v = x[g];
    __half hh = __float2half_rn(v);
    float hf = __half2float(hh);
    size_t b = (size_t)m * KH + sp16(k);
    g_xc[b]        = hh;
    g_xc[b + 1024] = __float2half_rn(hf * (1.0f / SC));
    g_xc[b + 2048] = __float2half_rn((v - hf) * SC);
}

__global__ void tr_wp(const float* __restrict__ Wp) {
    __shared__ float t[32][33];
    int n0 = blockIdx.x * 32, k0 = blockIdx.y * 32;
    int tx = threadIdx.x, ty = threadIdx.y;
    #pragma unroll
    for (int i = 0; i < 4; i++)
        t[ty + i * 8][tx] = Wp[(size_t)(k0 + ty + i * 8) * (RNUM * 256) + n0 + tx];
    __syncthreads();
    #pragma unroll
    for (int i = 0; i < 4; i++) {
        int rr = ty + i * 8;
        float v = t[tx][rr];
        __half hh = __float2half_rn(v);
        float hf = __half2float(hh);
        int p = sp16(k0 + tx);
        size_t b = (size_t)(n0 + rr) * KH;
        g_wpc[b + p]        = hh;
        g_wpc[b + 1024 + p] = __float2half_rn((v - hf) * SC);
        g_wpc[b + 2048 + p] = __float2half_rn(hf * (1.0f / SC));
    }
}

__global__ void tr_wc(const float* __restrict__ Wd, const float* __restrict__ Wa) {
    __shared__ float t[2][32][33];
    int n0 = blockIdx.x * 32, k0 = blockIdx.y * 32;
    int tx = threadIdx.x, ty = threadIdx.y;
    #pragma unroll
    for (int i = 0; i < 4; i++) {
        int rr = ty + i * 8;
        t[0][rr][tx] = Wd[(size_t)(k0 + rr) * DM + n0 + tx];
        t[1][rr][tx] = Wa[(size_t)(k0 + rr) * DM + n0 + tx];
    }
    __syncthreads();
    #pragma unroll
    for (int i = 0; i < 4; i++) {
        int rr = ty + i * 8;
        int p = sp16(k0 + tx);
        #pragma unroll
        for (int s = 0; s < 2; s++) {
            float v = t[s][tx][rr];
            __half hh = __float2half_rn(v);
            float hf = __half2float(hh);
            size_t b = (size_t)(2 * (n0 + rr) + s) * KH;
            g_wc[b + p]        = hh;
            g_wc[b + 1024 + p] = __float2half_rn((v - hf) * SC);
            g_wc[b + 2048 + p] = __float2half_rn(hf * (1.0f / SC));
        }
    }
}

// ---------------- GEMM building blocks ----------------
__device__ __forceinline__ void ld_tile(uint32_t sA, uint32_t sB,
                                        const __half* Ag, const __half* Bg,
                                        int gk, int tid) {
    #pragma unroll
    for (int i = 0; i < 4; i++) {
        int v = tid + i * 256, row = v >> 3, c = v & 7;
        CPA16(sA + row * RSTR + c * 16, (const char*)(Ag + (size_t)row * KH + gk) + c * 16);
    }
    #pragma unroll
    for (int i = 0; i < 8; i++) {
        int v = tid + i * 256, row = v >> 3, c = v & 7;
        CPA16(sB + row * RSTR + c * 16, (const char*)(Bg + (size_t)row * KH + gk) + c * 16);
    }
}

__device__ __forceinline__ void compute_tile(uint32_t sA, uint32_t sB,
                                             int wm, int wn, int gid, int qc,
                                             float acc[4][8][4]) {
    #pragma unroll
    for (int ks = 0; ks < 4; ks++) {
        uint32_t coff = ks * 32 + qc * 8;
        uint32_t A0[4], A1[4], A2[4], A3[4], B0[8], B1[8];
        #pragma unroll
        for (int fm = 0; fm < 4; fm++) {
            uint32_t a = sA + (wm + fm * 16 + gid) * RSTR + coff;
            lds64(A0[fm], A2[fm], a);
            lds64(A1[fm], A3[fm], a + 8 * RSTR);
        }
        #pragma unroll
        for (int fn = 0; fn < 8; fn++)
            lds64(B0[fn], B1[fn], sB + (wn + fn * 8 + gid) * RSTR + coff);
        #pragma unroll
        for (int fm = 0; fm < 4; fm++)
            #pragma unroll
            for (int fn = 0; fn < 8; fn++)
                MMA_F16(acc[fm][fn], A0[fm], A1[fm], A2[fm], A3[fm], B0[fn], B1[fn]);
    }
}

#define GEMM_MAINLOOP(Ag, Bg)                                                   \
    float acc[4][8][4] = {};                                                    \
    ld_tile(sb, sb + ASZ, Ag, Bg, 0, tid); CP_COMMIT();                         \
    ld_tile(sb + STG, sb + STG + ASZ, Ag, Bg, KT, tid); CP_COMMIT();            \
    for (int kt = 0; kt < NKT; kt++) {                                          \
        if (kt + 1 < NKT) { CP_WAIT(1); } else { CP_WAIT(0); }                  \
        __syncthreads();                                                        \
        if (kt + 2 < NKT) {                                                     \
            uint32_t pb = sb + ((kt + 2) % 3) * STG;                            \
            ld_tile(pb, pb + ASZ, Ag, Bg, (kt + 2) * KT, tid); CP_COMMIT();     \
        }                                                                       \
        uint32_t st = sb + (kt % 3) * STG;                                      \
        compute_tile(st, st + ASZ, wm, wn, gid, qc, acc);                       \
    }                                                                           \
    __syncthreads();

// ---------------- diag kernel (256 thr, 128x256) ----------------
__global__ __launch_bounds__(256, 1) void diag_mma() {
    extern __shared__ __align__(16) char smem[];
    uint32_t sb = smem_u32(smem);
    const int tid = threadIdx.x, wid = tid >> 5, lane = tid & 31;
    const int m0 = blockIdx.x * 128, n0 = blockIdx.y * 256;
    const int wm = (wid & 1) * 64, wn = (wid >> 1) * 64;
    const int gid = lane >> 2, qc = lane & 3;

    GEMM_MAINLOOP(g_xc + (size_t)m0 * KH, g_wc + (size_t)n0 * KH)

    #pragma unroll
    for (int fm = 0; fm < 4; fm++)
        #pragma unroll
        for (int fn = 0; fn < 8; fn++) {
            int mm = m0 + wm + fm * 16 + gid;
            int tcol = (n0 + wn + fn * 8 + 2 * qc) >> 1;
            float* c = acc[fm][fn];
            float s0 = 1.0f / (1.0f + expf(-c[1]));
            float s1 = 1.0f / (1.0f + expf(-c[3]));
            g_dv[(size_t)mm * DM + tcol]       = s0 * tanhf(c[0]);
            g_dv[(size_t)(mm + 8) * DM + tcol] = s1 * tanhf(c[2]);
        }
}

// ---------------- perm kernel (256 thr, 128x256) ----------------
__global__ __launch_bounds__(256, 1) void perm_mma(const float* __restrict__ h,
                                                   float* __restrict__ out) {
    extern __shared__ __align__(16) char smem[];
    uint32_t sb = smem_u32(smem);
    const int tid = threadIdx.x, wid = tid >> 5, lane = tid & 31;
    const int m0 = blockIdx.x * 128, r = blockIdx.y;
    const int wm = (wid & 1) * 64, wn = (wid >> 1) * 64;
    const int gid = lane >> 2, qc = lane & 3;

    GEMM_MAINLOOP(g_xc + (size_t)m0 * KH, g_wpc + (size_t)r * 256 * KH)

    float* Csm = (float*)smem;
    #pragma unroll
    for (int fm = 0; fm < 4; fm++)
        #pragma unroll
        for (int fn = 0; fn < 8; fn++) {
            int mm = wm + fm * 16 + gid, nn = wn + fn * 8 + 2 * qc;
            float* c = acc[fm][fn];
            Csm[mm * CSTR + nn]           = c[0];
            Csm[mm * CSTR + nn + 1]       = c[1];
            Csm[(mm + 8) * CSTR + nn]     = c[2];
            Csm[(mm + 8) * CSTR + nn + 1] = c[3];
        }
    __syncthreads();

    // ---- sinkhorn + argmax (+ near-tie flag) + permute ----
    const int j = lane & 15, gb = (lane >> 4) << 4;
    const unsigned FULL = 0xffffffffu;

    #pragma unroll 1
    for (int pass = 0; pass < 8; pass++) {
        int m = pass * 16 + (tid >> 4);
        float la[16];
        #pragma unroll
        for (int i = 0; i < 16; i++)
            la[i] = 2.0f * Csm[m * CSTR + i * 16 + j];   // /TAU (TAU=0.5)

        #pragma unroll 1
        for (int it = 0; it < 5; it++) {
            #pragma unroll
            for (int i = 0; i < 16; i++) {
                float mx = la[i];
                mx = fmaxf(mx, __shfl_xor_sync(FULL, mx, 1));
                mx = fmaxf(mx, __shfl_xor_sync(FULL, mx, 2));
                mx = fmaxf(mx, __shfl_xor_sync(FULL, mx, 4));
                mx = fmaxf(mx, __shfl_xor_sync(FULL, mx, 8));
                float e = __expf(la[i] - mx);
                e += __shfl_xor_sync(FULL, e, 1);
                e += __shfl_xor_sync(FULL, e, 2);
                e += __shfl_xor_sync(FULL, e, 4);
                e += __shfl_xor_sync(FULL, e, 8);
                la[i] -= mx + __logf(e);
            }
            if (it < 4) {   // final col-norm is argmax-invariant: skip
                float mx = la[0];
                #pragma unroll
                for (int i = 1; i < 16; i++) mx = fmaxf(mx, la[i]);
                float ssum = 0.f;
                #pragma unroll
                for (int i = 0; i < 16; i++) ssum += __expf(la[i] - mx);
                float sub = mx + __logf(ssum);
                #pragma unroll
                for (int i = 0; i < 16; i++) la[i] -= sub;
            }
        }

        int best = 0; float bv = la[0], sv = -1e30f;
        #pragma unroll
        for (int i = 1; i < 16; i++) {
            if (la[i] > bv) { sv = bv; bv = la[i]; best = i; }
            else if (la[i] > sv) sv = la[i];
        }

        int bg = m0 + m;

        unsigned bal = __ballot_sync(FULL, (bv - sv) < TIE_EPS);
        if (((bal >> gb) & 0xFFFFu) && lane == gb) {
            int idx = atomicAdd(&g_cnt, 1);
            if (idx < MAXF) g_flags[idx] = make_int2(bg, r);
        }

        float hv = h[(size_t)bg * DM + r * 16 + j];
        float hp = 0.f;
        #pragma unroll
        for (int jj = 0; jj < 16; jj++) {
            int   ib = __shfl_sync(FULL, best, gb + jj);
            float hj = __shfl_sync(FULL, hv,   gb + jj);
            if (ib == j) hp += hj;
        }
        int oi = bg * DM + r * 16 + j;
        out[oi] = g_dv[oi] * hp;
    }
}

// ---------------- exact fixup from ORIGINAL fp32 inputs (rare) ----------------
__global__ void fixup(const float* __restrict__ x, const float* __restrict__ Wp,
                      const float* __restrict__ h, float* __restrict__ out) {
    __shared__ float xs[1024];
    __shared__ double Ls[256];
    int n = g_cnt; if (n > MAXF) n = MAXF;
    const int tid = threadIdx.x;

    for (int f = blockIdx.x; f < n; f += gridDim.x) {
        int bg = g_flags[f].x, r = g_flags[f].y;
        __syncthreads();
        for (int k = tid; k < 1024; k += 256) xs[k] = x[(size_t)bg * DM + k];
        __syncthreads();

        {
            int col = r * 256 + tid;           // tid = i*16+j over the 16x16 block
            double s = 0.0;
            #pragma unroll 4
            for (int k = 0; k < 1024; k++)
                s += (double)xs[k] * (double)Wp[(size_t)k * (RNUM * 256) + col];
            Ls[tid] = 2.0 * s;
        }
        __syncthreads();

        if (tid < 16) {
            const unsigned M16 = 0xFFFFu;
            int j = tid;
            double L[16];
            #pragma unroll
            for (int i = 0; i < 16; i++) L[i] = Ls[i * 16 + j];
            #pragma unroll 1
            for (int it = 0; it < 5; it++) {
                #pragma unroll 1
                for (int i = 0; i < 16; i++) {
                    double mx = L[i];
                    mx = fmax(mx, __shfl_xor_sync(M16, mx, 1));
                    mx = fmax(mx, __shfl_xor_sync(M16, mx, 2));
                    mx = fmax(mx, __shfl_xor_sync(M16, mx, 4));
                    mx = fmax(mx, __shfl_xor_sync(M16, mx, 8));
                    double e = exp(L[i] - mx);
                    e += __shfl_xor_sync(M16, e, 1);
                    e += __shfl_xor_sync(M16, e, 2);
                    e += __shfl_xor_sync(M16, e, 4);
                    e += __shfl_xor_sync(M16, e, 8);
                    L[i] -= mx + log(e);
                }
                if (it < 4) {
                    double mx = L[0];
                    #pragma unroll
                    for (int i = 1; i < 16; i++) mx = fmax(mx, L[i]);
                    double ss = 0.0;
                    #pragma unroll
                    for (int i = 0; i < 16; i++) ss += exp(L[i] - mx);
                    double sub = mx + log(ss);
                    #pragma unroll
                    for (int i = 0; i < 16; i++) L[i] -= sub;
                }
            }
            int best = 0; double bv = L[0];
            #pragma unroll
            for (int i = 1; i < 16; i++)
                if (L[i] > bv) { bv = L[i]; best = i; }

            float hv = h[(size_t)bg * DM + r * 16 + j];
            float hp = 0.f;
            #pragma unroll
            for (int jj = 0; jj < 16; jj++) {
                int   ib = __shfl_sync(M16, best, jj);
                float hj = __shfl_sync(M16, hv,   jj);
                if (ib == j) hp += hj;
            }
            int oi = bg * DM + r * 16 + j;
            out[oi] = g_dv[oi] * hp;
        }
        __syncthreads();
    }
}

// ---------------- launch ----------------
extern "C" void kernel_launch(void* const* d_in, const int* in_sizes, int n_in,
                              void* d_out, int out_size) {
    const float* x  = (const float*)d_in[0];
    const float* h  = (const float*)d_in[1];
    const float* Wp = (const float*)d_in[2];
    const float* Wd = (const float*)d_in[3];
    const float* Wa = (const float*)d_in[4];
    float* out = (float*)d_out;

    cudaFuncSetAttribute(perm_mma, cudaFuncAttributeMaxDynamicSharedMemorySize, SMEMSZ);
    cudaFuncSetAttribute(diag_mma, cudaFuncAttributeMaxDynamicSharedMemorySize, SMEMSZ);

    conv_x<<<BATCH * DM / 256, 256>>>(x);
    tr_wp<<<dim3(512, 32), dim3(32, 8)>>>(Wp);
    tr_wc<<<dim3(32, 32), dim3(32, 8)>>>(Wd, Wa);
    diag_mma<<<dim3(16, 8), 256, SMEMSZ>>>();
    perm_mma<<<dim3(16, 64), 256, SMEMSZ>>>(h, out);
    fixup<<<256, 256>>>(x, Wp, h, out);
}

// round 8
// speedup vs baseline: 3.9311x; 1.0730x over previous
#include <cuda_runtime.h>
#include <cuda_fp16.h>
#include <cstdint>
#include <math.h>

#define BATCH 2048
#define DM    1024
#define RNUM  64
#define KH    3072          // concat K in halfs
#define KT    64            // k-tile in halfs (128 B rows)
#define NKT   (KH / KT)     // 48
#define ABLK  8192          // A tile block halfs (128 x 64) = 16 KB
#define BBLK  16384         // B tile block halfs (256 x 64) = 32 KB
#define STGB  49152         // stage bytes (A+B)
#define CSTR  257
#define TIE_EPS 1.5e-5f
#define MAXF  16384
#define SMEMSZ (1024 + 3 * STGB)
#define SC    64.0f

// ---------------- device scratch ----------------
__device__ float  g_dv[BATCH * DM];
__device__ __half g_xc[BATCH * KH];           // tiled [mtile][kt][row128][64] swizzled
__device__ __half g_wpc[RNUM * 256 * KH];     // tiled [r][kt][row256][64]
__device__ __half g_wc[2 * DM * KH];          // tiled [nt8][kt][row256][64]
__device__ int    g_cnt;
__device__ int2   g_flags[MAXF];

// ---------------- helpers ----------------
__device__ __forceinline__ uint32_t smem_u32(const void* p) {
    uint32_t a;
    asm("{ .reg .u64 t; cvta.to.shared.u64 t, %1; cvt.u32.u64 %0, t; }" : "=r"(a) : "l"(p));
    return a;
}
// within-16 fragment permutation (logical k -> concat position)
__device__ __forceinline__ int sp16(int k) {
    return (k & ~15) | ((k & 6) << 1) | ((k & 8) >> 2) | (k & 1);
}
__device__ __forceinline__ void lds64(uint32_t& r0, uint32_t& r1, uint32_t a) {
    asm volatile("ld.shared.v2.b32 {%0,%1}, [%2];" : "=r"(r0), "=r"(r1) : "r"(a));
}
#define MBAR_INIT(a, c) asm volatile("mbarrier.init.shared.b64 [%0], %1;" :: "r"(a), "r"(c) : "memory")
#define MBAR_EXPECT(a, b) asm volatile("mbarrier.arrive.expect_tx.shared.b64 _, [%0], %1;" :: "r"(a), "r"(b) : "memory")
#define BULK(dst, src, sz, mb) \
    asm volatile("cp.async.bulk.shared::cluster.global.mbarrier::complete_tx::bytes [%0], [%1], %2, [%3];" \
                 :: "r"(dst), "l"(src), "r"(sz), "r"(mb) : "memory")
__device__ __forceinline__ void mbar_wait(uint32_t a, uint32_t ph) {
    asm volatile(
        "{\n.reg .pred P;\n"
        "WL%=:\n"
        "mbarrier.try_wait.parity.acquire.cta.shared::cta.b64 P, [%0], %1, 0x989680;\n"
        "@P bra WD%=;\n"
        "bra WL%=;\n"
        "WD%=:\n}"
        :: "r"(a), "r"(ph) : "memory");
}

#define MMA_F16(c, a0, a1, a2, a3, b0, b1) \
    asm volatile("mma.sync.aligned.m16n8k16.row.col.f32.f16.f16.f32 " \
        "{%0,%1,%2,%3}, {%4,%5,%6,%7}, {%8,%9}, {%0,%1,%2,%3};" \
        : "+f"((c)[0]), "+f"((c)[1]), "+f"((c)[2]), "+f"((c)[3]) \
        : "r"(a0), "r"(a1), "r"(a2), "r"(a3), "r"(b0), "r"(b1))

// ---------------- prep kernels (write tiled + swizzled layouts) ----------------
__device__ __forceinline__ size_t a_idx(int m, int p) {
    int row = m & 127;
    return ((size_t)((m >> 7) * NKT + (p >> 6)) * 128 + row) * 64 +
           ((p & 63) ^ ((row & 3) << 4));
}
__device__ __forceinline__ size_t b_idx(int blk, int row, int p) {
    return ((size_t)(blk * NKT + (p >> 6)) * 256 + row) * 64 +
           ((p & 63) ^ ((row & 3) << 4));
}

__global__ void conv_x(const float* __restrict__ x) {
    int g = blockIdx.x * 256 + threadIdx.x;
    if (g == 0) g_cnt = 0;
    int m = g >> 10, k = g & 1023;
    float v = x[g];
    __half hh = __float2half_rn(v);
    float hf = __half2float(hh);
    int p = sp16(k);
    g_xc[a_idx(m, p)]        = hh;
    g_xc[a_idx(m, p + 1024)] = __float2half_rn(hf * (1.0f / SC));
    g_xc[a_idx(m, p + 2048)] = __float2half_rn((v - hf) * SC);
}

__global__ void tr_wp(const float* __restrict__ Wp) {
    __shared__ float t[32][33];
    int n0 = blockIdx.x * 32, k0 = blockIdx.y * 32;
    int tx = threadIdx.x, ty = threadIdx.y;
    #pragma unroll
    for (int i = 0; i < 4; i++)
        t[ty + i * 8][tx] = Wp[(size_t)(k0 + ty + i * 8) * (RNUM * 256) + n0 + tx];
    __syncthreads();
    #pragma unroll
    for (int i = 0; i < 4; i++) {
        int rr = ty + i * 8;
        int n = n0 + rr;
        float v = t[tx][rr];
        __half hh = __float2half_rn(v);
        float hf = __half2float(hh);
        int p = sp16(k0 + tx);
        int r = n >> 8, nr = n & 255;
        g_wpc[b_idx(r, nr, p)]        = hh;
        g_wpc[b_idx(r, nr, p + 1024)] = __float2half_rn((v - hf) * SC);
        g_wpc[b_idx(r, nr, p + 2048)] = __float2half_rn(hf * (1.0f / SC));
    }
}

__global__ void tr_wc(const float* __restrict__ Wd, const float* __restrict__ Wa) {
    __shared__ float t[2][32][33];
    int n0 = blockIdx.x * 32, k0 = blockIdx.y * 32;
    int tx = threadIdx.x, ty = threadIdx.y;
    #pragma unroll
    for (int i = 0; i < 4; i++) {
        int rr = ty + i * 8;
        t[0][rr][tx] = Wd[(size_t)(k0 + rr) * DM + n0 + tx];
        t[1][rr][tx] = Wa[(size_t)(k0 + rr) * DM + n0 + tx];
    }
    __syncthreads();
    #pragma unroll
    for (int i = 0; i < 4; i++) {
        int rr = ty + i * 8;
        int p = sp16(k0 + tx);
        #pragma unroll
        for (int s = 0; s < 2; s++) {
            float v = t[s][tx][rr];
            __half hh = __float2half_rn(v);
            float hf = __half2float(hh);
            int col2 = 2 * (n0 + rr) + s;
            int nt = col2 >> 8, row = col2 & 255;
            g_wc[b_idx(nt, row, p)]        = hh;
            g_wc[b_idx(nt, row, p + 1024)] = __float2half_rn((v - hf) * SC);
            g_wc[b_idx(nt, row, p + 2048)] = __float2half_rn(hf * (1.0f / SC));
        }
    }
}

// ---------------- GEMM core ----------------
__device__ __forceinline__ void compute_tile(uint32_t sA, uint32_t sB,
                                             int wm, int wn, int gid, int qc,
                                             float acc[4][8][4]) {
    #pragma unroll
    for (int ks = 0; ks < 4; ks++) {
        uint32_t sw = (uint32_t)(ks * 32 + qc * 8) ^ (uint32_t)((gid & 3) << 5);
        uint32_t A0[4], A1[4], A2[4], A3[4], B0[8], B1[8];
        #pragma unroll
        for (int fm = 0; fm < 4; fm++) {
            uint32_t a = sA + (wm + fm * 16 + gid) * 128 + sw;
            lds64(A0[fm], A2[fm], a);
            lds64(A1[fm], A3[fm], a + 8 * 128);
        }
        #pragma unroll
        for (int fn = 0; fn < 8; fn++)
            lds64(B0[fn], B1[fn], sB + (wn + fn * 8 + gid) * 128 + sw);
        #pragma unroll
        for (int fm = 0; fm < 4; fm++)
            #pragma unroll
            for (int fn = 0; fn < 8; fn++)
                MMA_F16(acc[fm][fn], A0[fm], A1[fm], A2[fm], A3[fm], B0[fn], B1[fn]);
    }
}

// 3-stage bulk-copy pipeline, one barrier per k-tile
#define GEMM_MAINLOOP(Ablocks, Bblocks)                                         \
    float acc[4][8][4] = {};                                                    \
    if (tid == 0) {                                                             \
        MBAR_INIT(sb + 16, 1); MBAR_INIT(sb + 24, 1); MBAR_INIT(sb + 32, 1);    \
    }                                                                           \
    __syncthreads();                                                            \
    if (tid == 0) {                                                             \
        _Pragma("unroll")                                                       \
        for (int s = 0; s < 2; s++) {                                           \
            uint32_t mb = sb + 16 + 8 * s, st = sb + 1024 + s * STGB;           \
            MBAR_EXPECT(mb, STGB);                                              \
            BULK(st, (const char*)(Ablocks + (size_t)s * ABLK), 16384, mb);     \
            BULK(st + 16384, (const char*)(Bblocks + (size_t)s * BBLK), 32768, mb); \
        }                                                                       \
    }                                                                           \
    for (int kt = 0; kt < NKT; kt++) {                                          \
        int s = kt % 3;                                                         \
        mbar_wait(sb + 16 + 8 * s, (kt / 3) & 1);                               \
        __syncthreads();                                                        \
        if (kt + 2 < NKT && tid == 0) {                                         \
            int s2 = (kt + 2) % 3;                                              \
            uint32_t mb = sb + 16 + 8 * s2, st = sb + 1024 + s2 * STGB;         \
            MBAR_EXPECT(mb, STGB);                                              \
            BULK(st, (const char*)(Ablocks + (size_t)(kt + 2) * ABLK), 16384, mb); \
            BULK(st + 16384, (const char*)(Bblocks + (size_t)(kt + 2) * BBLK), 32768, mb); \
        }                                                                       \
        uint32_t st = sb + 1024 + s * STGB;                                     \
        compute_tile(st, st + 16384, wm, wn, gid, qc, acc);                     \
    }                                                                           \
    __syncthreads();

// ---------------- diag kernel ----------------
__global__ __launch_bounds__(256, 1) void diag_mma() {
    extern __shared__ __align__(1024) char smem[];
    uint32_t sb = smem_u32(smem);
    const int tid = threadIdx.x, wid = tid >> 5, lane = tid & 31;
    const int m0 = blockIdx.x * 128, nt = blockIdx.y;
    const int wm = (wid & 1) * 64, wn = (wid >> 1) * 64;
    const int gid = lane >> 2, qc = lane & 3;
    const int n0 = nt * 256;

    const __half* Ab = g_xc + (size_t)blockIdx.x * NKT * ABLK;
    const __half* Bb = g_wc + (size_t)nt * NKT * BBLK;
    GEMM_MAINLOOP(Ab, Bb)

    #pragma unroll
    for (int fm = 0; fm < 4; fm++)
        #pragma unroll
        for (int fn = 0; fn < 8; fn++) {
            int mm = m0 + wm + fm * 16 + gid;
            int tcol = (n0 + wn + fn * 8 + 2 * qc) >> 1;
            float* c = acc[fm][fn];
            float s0 = 1.0f / (1.0f + expf(-c[1]));
            float s1 = 1.0f / (1.0f + expf(-c[3]));
            g_dv[(size_t)mm * DM + tcol]       = s0 * tanhf(c[0]);
            g_dv[(size_t)(mm + 8) * DM + tcol] = s1 * tanhf(c[2]);
        }
}

// ---------------- perm kernel ----------------
__global__ __launch_bounds__(256, 1) void perm_mma(const float* __restrict__ h,
                                                   float* __restrict__ out) {
    extern __shared__ __align__(1024) char smem[];
    uint32_t sb = smem_u32(smem);
    const int tid = threadIdx.x, wid = tid >> 5, lane = tid & 31;
    const int m0 = blockIdx.x * 128, r = blockIdx.y;
    const int wm = (wid & 1) * 64, wn = (wid >> 1) * 64;
    const int gid = lane >> 2, qc = lane & 3;

    const __half* Ab = g_xc + (size_t)blockIdx.x * NKT * ABLK;
    const __half* Bb = g_wpc + (size_t)r * NKT * BBLK;
    GEMM_MAINLOOP(Ab, Bb)

    float* Csm = (float*)smem;
    #pragma unroll
    for (int fm = 0; fm < 4; fm++)
        #pragma unroll
        for (int fn = 0; fn < 8; fn++) {
            int mm = wm + fm * 16 + gid, nn = wn + fn * 8 + 2 * qc;
            float* c = acc[fm][fn];
            Csm[mm * CSTR + nn]           = c[0];
            Csm[mm * CSTR + nn + 1]       = c[1];
            Csm[(mm + 8) * CSTR + nn]     = c[2];
            Csm[(mm + 8) * CSTR + nn + 1] = c[3];
        }
    __syncthreads();

    // ---- sinkhorn + argmax (+ near-tie flag) + permute ----
    const int j = lane & 15, gb = (lane >> 4) << 4;
    const unsigned FULL = 0xffffffffu;

    #pragma unroll 1
    for (int pass = 0; pass < 8; pass++) {
        int m = pass * 16 + (tid >> 4);
        float la[16];
        #pragma unroll
        for (int i = 0; i < 16; i++)
            la[i] = 2.0f * Csm[m * CSTR + i * 16 + j];   // /TAU (TAU=0.5)

        #pragma unroll 1
        for (int it = 0; it < 5; it++) {
            #pragma unroll
            for (int i = 0; i < 16; i++) {
                float mx = la[i];
                mx = fmaxf(mx, __shfl_xor_sync(FULL, mx, 1));
                mx = fmaxf(mx, __shfl_xor_sync(FULL, mx, 2));
                mx = fmaxf(mx, __shfl_xor_sync(FULL, mx, 4));
                mx = fmaxf(mx, __shfl_xor_sync(FULL, mx, 8));
                float e = __expf(la[i] - mx);
                e += __shfl_xor_sync(FULL, e, 1);
                e += __shfl_xor_sync(FULL, e, 2);
                e += __shfl_xor_sync(FULL, e, 4);
                e += __shfl_xor_sync(FULL, e, 8);
                la[i] -= mx + __logf(e);
            }
            if (it < 4) {   // final col-norm is argmax-invariant: skip
                float mx = la[0];
                #pragma unroll
                for (int i = 1; i < 16; i++) mx = fmaxf(mx, la[i]);
                float ssum = 0.f;
                #pragma unroll
                for (int i = 0; i < 16; i++) ssum += __expf(la[i] - mx);
                float sub = mx + __logf(ssum);
                #pragma unroll
                for (int i = 0; i < 16; i++) la[i] -= sub;
            }
        }

        int best = 0; float bv = la[0], sv = -1e30f;
        #pragma unroll
        for (int i = 1; i < 16; i++) {
            if (la[i] > bv) { sv = bv; bv = la[i]; best = i; }
            else if (la[i] > sv) sv = la[i];
        }

        int bg = m0 + m;

        unsigned bal = __ballot_sync(FULL, (bv - sv) < TIE_EPS);
        if (((bal >> gb) & 0xFFFFu) && lane == gb) {
            int idx = atomicAdd(&g_cnt, 1);
            if (idx < MAXF) g_flags[idx] = make_int2(bg, r);
        }

        float hv = h[(size_t)bg * DM + r * 16 + j];
        float hp = 0.f;
        #pragma unroll
        for (int jj = 0; jj < 16; jj++) {
            int   ib = __shfl_sync(FULL, best, gb + jj);
            float hj = __shfl_sync(FULL, hv,   gb + jj);
            if (ib == j) hp += hj;
        }
        int oi = bg * DM + r * 16 + j;
        out[oi] = g_dv[oi] * hp;
    }
}

// ---------------- exact fixup from ORIGINAL fp32 inputs (rare) ----------------
__global__ void fixup(const float* __restrict__ x, const float* __restrict__ Wp,
                      const float* __restrict__ h, float* __restrict__ out) {
    __shared__ float xs[1024];
    __shared__ double Ls[256];
    int n = g_cnt; if (n > MAXF) n = MAXF;
    const int tid = threadIdx.x;

    for (int f = blockIdx.x; f < n; f += gridDim.x) {
        int bg = g_flags[f].x, r = g_flags[f].y;
        __syncthreads();
        for (int k = tid; k < 1024; k += 256) xs[k] = x[(size_t)bg * DM + k];
        __syncthreads();

        {
            int col = r * 256 + tid;
            double s = 0.0;
            #pragma unroll 4
            for (int k = 0; k < 1024; k++)
                s += (double)xs[k] * (double)Wp[(size_t)k * (RNUM * 256) + col];
            Ls[tid] = 2.0 * s;
        }
        __syncthreads();

        if (tid < 16) {
            const unsigned M16 = 0xFFFFu;
            int j = tid;
            double L[16];
            #pragma unroll
            for (int i = 0; i < 16; i++) L[i] = Ls[i * 16 + j];
            #pragma unroll 1
            for (int it = 0; it < 5; it++) {
                #pragma unroll 1
                for (int i = 0; i < 16; i++) {
                    double mx = L[i];
                    mx = fmax(mx, __shfl_xor_sync(M16, mx, 1));
                    mx = fmax(mx, __shfl_xor_sync(M16, mx, 2));
                    mx = fmax(mx, __shfl_xor_sync(M16, mx, 4));
                    mx = fmax(mx, __shfl_xor_sync(M16, mx, 8));
                    double e = exp(L[i] - mx);
                    e += __shfl_xor_sync(M16, e, 1);
                    e += __shfl_xor_sync(M16, e, 2);
                    e += __shfl_xor_sync(M16, e, 4);
                    e += __shfl_xor_sync(M16, e, 8);
                    L[i] -= mx + log(e);
                }
                if (it < 4) {
                    double mx = L[0];
                    #pragma unroll
                    for (int i = 1; i < 16; i++) mx = fmax(mx, L[i]);
                    double ss = 0.0;
                    #pragma unroll
                    for (int i = 0; i < 16; i++) ss += exp(L[i] - mx);
                    double sub = mx + log(ss);
                    #pragma unroll
                    for (int i = 0; i < 16; i++) L[i] -= sub;
                }
            }
            int best = 0; double bv = L[0];
            #pragma unroll
            for (int i = 1; i < 16; i++)
                if (L[i] > bv) { bv = L[i]; best = i; }

            float hv = h[(size_t)bg * DM + r * 16 + j];
            float hp = 0.f;
            #pragma unroll
            for (int jj = 0; jj < 16; jj++) {
                int   ib = __shfl_sync(M16, best, jj);
                float hj = __shfl_sync(M16, hv,   jj);
                if (ib == j) hp += hj;
            }
            int oi = bg * DM + r * 16 + j;
            out[oi] = g_dv[oi] * hp;
        }
        __syncthreads();
    }
}

// ---------------- launch ----------------
extern "C" void kernel_launch(void* const* d_in, const int* in_sizes, int n_in,
                              void* d_out, int out_size) {
    const float* x  = (const float*)d_in[0];
    const float* h  = (const float*)d_in[1];
    const float* Wp = (const float*)d_in[2];
    const float* Wd = (const float*)d_in[3];
    const float* Wa = (const float*)d_in[4];
    float* out = (float*)d_out;

    cudaFuncSetAttribute(perm_mma, cudaFuncAttributeMaxDynamicSharedMemorySize, SMEMSZ);
    cudaFuncSetAttribute(diag_mma, cudaFuncAttributeMaxDynamicSharedMemorySize, SMEMSZ);

    conv_x<<<BATCH * DM / 256, 256>>>(x);
    tr_wp<<<dim3(512, 32), dim3(32, 8)>>>(Wp);
    tr_wc<<<dim3(32, 32), dim3(32, 8)>>>(Wd, Wa);
    diag_mma<<<dim3(16, 8), 256, SMEMSZ>>>();
    perm_mma<<<dim3(16, 64), 256, SMEMSZ>>>(h, out);
    fixup<<<256, 256>>>(x, Wp, h, out);
}